// round 11
// baseline (speedup 1.0000x reference)
#include <cuda_runtime.h>

#define BB   32
#define EE   48
#define MM   96
#define DD   256
#define HH   8
#define DPH  32
#define PAIRS (EE*EE)
#define MAXML 64
#define SCAP 8

// ---------------- scratch ----------------
__device__ int   g_sidx[BB*MM];
__device__ int   g_mlist[BB*EE*MAXML];
__device__ int   g_mcnt [BB*EE];
__device__ float g_qp [2][BB*EE*DD];
__device__ float g_kp [2][BB*MM*DD];
__device__ float g_v  [2][BB*MM*DD];
__device__ float g_voh[2][BB*MM*HH*DD];
__device__ float g_sc [2][BB*EE*HH*MM];

__device__ __forceinline__ void fma2(float2& d, float2 a, float2 b) {
    unsigned long long dd = *(unsigned long long*)&d;
    unsigned long long aa = *(unsigned long long*)&a;
    unsigned long long bb = *(unsigned long long*)&b;
    asm("fma.rn.f32x2 %0, %1, %2, %0;" : "+l"(dd) : "l"(aa), "l"(bb));
    d = *(float2*)&dd;
}

__device__ __forceinline__ float4 ldg4(const float* p) {
    return __ldg((const float4*)p);
}

// ---------------- prep: one block per doc ----------------
__global__ void k_prep(const void* info) {
    int b = blockIdx.x, tid = threadIdx.x;
    __shared__ int smid[MM];
    __shared__ int s[128];
    const int* p32 = (const int*)info;
    int mx = 0;
    for (int r = tid; r < BB*MM; r += 128) mx = max(mx, p32[r*6 + 4]);
    s[tid] = mx; __syncthreads();
    for (int o = 64; o > 0; o >>= 1) { if (tid < o) s[tid] = max(s[tid], s[tid+o]); __syncthreads(); }
    int is32 = (s[0] > 0);
    for (int m = tid; m < MM; m += 128) {
        int r = b*MM + m;
        int e, sidx;
        if (is32) { e = p32[r*6 + 0]; sidx = p32[r*6 + 4]; }
        else {
            const long long* p64 = (const long long*)info;
            e = (int)p64[r*6 + 0]; sidx = (int)p64[r*6 + 4];
        }
        smid[m] = e; g_sidx[r] = sidx;
    }
    __syncthreads();
    for (int e = tid; e < EE; e += 128) {
        int target = b*EE + e;
        int cnt = 0;
        for (int m = 0; m < MM; m++) {
            if (smid[m] == target && cnt < MAXML)
                g_mlist[target*MAXML + cnt++] = m;
        }
        g_mcnt[target] = cnt;
    }
}

// ---------------- all 6 projections: 128x128 tiles, KSTEP=16, f32x2 ----------------
__global__ __launch_bounds__(256, 2) void k_proj_all(
    const float* __restrict__ ent, const float* __restrict__ men, const float* __restrict__ sen,
    const float* __restrict__ W1, const float* __restrict__ b1,
    const float* __restrict__ W2, const float* __restrict__ b2)
{
    __shared__ float2 As2[16][128];
    __shared__ float2 Ws2[16][64];

    int blk = blockIdx.x;
    int cb = blk & 1, rb = blk >> 1;
    int set = rb / 60; int r = rb % 60;
    const float* A; int gather = 0, type, row0;
    if (r < 12)      { type = 0; row0 = r*128;      A = ent; }
    else if (r < 36) { type = 1; row0 = (r-12)*128; A = sen; gather = 1; }
    else             { type = 2; row0 = (r-36)*128; A = men; }
    const float* W  = (set ? W2 : W1) + type*DD*DD;
    const float* bi = (set ? b2 : b1) + type*DD;
    float* C = (type == 0) ? g_qp[set] : (type == 1 ? g_kp[set] : g_v[set]);
    int n0 = cb*128;

    int tid = threadIdx.x;
    int tx = tid & 15, ty = tid >> 4;

    int am  = tid >> 1;
    int akq = (tid & 1) * 8;
    int arow = row0 + am;
    int asrc = gather ? g_sidx[arow] : arow;
    const float* aptr = A + (size_t)asrc*DD + akq;
    int wk = tid >> 4;
    int wn = (tid & 15) * 8;
    const float* wptr = W + (size_t)wk*DD + n0 + wn;
    int wp = (tid & 15) * 4;

    float2 acc2[8][4];
#pragma unroll
    for (int i = 0; i < 8; i++)
#pragma unroll
        for (int j = 0; j < 4; j++) acc2[i][j] = make_float2(0.f, 0.f);

    for (int k0 = 0; k0 < DD; k0 += 16) {
        float4 a0 = *(const float4*)(aptr + k0);
        float4 a1 = *(const float4*)(aptr + k0 + 4);
        float4 w0 = *(const float4*)(wptr + (size_t)k0*DD);
        float4 w1 = *(const float4*)(wptr + (size_t)k0*DD + 4);
        As2[akq+0][am] = make_float2(a0.x, a0.x);
        As2[akq+1][am] = make_float2(a0.y, a0.y);
        As2[akq+2][am] = make_float2(a0.z, a0.z);
        As2[akq+3][am] = make_float2(a0.w, a0.w);
        As2[akq+4][am] = make_float2(a1.x, a1.x);
        As2[akq+5][am] = make_float2(a1.y, a1.y);
        As2[akq+6][am] = make_float2(a1.z, a1.z);
        As2[akq+7][am] = make_float2(a1.w, a1.w);
        Ws2[wk][wp]   = make_float2(w0.x, w0.y);
        Ws2[wk][wp+1] = make_float2(w0.z, w0.w);
        Ws2[wk][wp+2] = make_float2(w1.x, w1.y);
        Ws2[wk][wp+3] = make_float2(w1.z, w1.w);
        __syncthreads();
#pragma unroll
        for (int kk = 0; kk < 16; kk++) {
            float2 a[8], bfr[4];
#pragma unroll
            for (int i = 0; i < 8; i++) a[i] = As2[kk][ty*8 + i];
#pragma unroll
            for (int j = 0; j < 4; j++) bfr[j] = Ws2[kk][tx*4 + j];
#pragma unroll
            for (int i = 0; i < 8; i++)
#pragma unroll
                for (int j = 0; j < 4; j++) fma2(acc2[i][j], a[i], bfr[j]);
        }
        __syncthreads();
    }

    float bj[8];
#pragma unroll
    for (int j = 0; j < 8; j++) bj[j] = bi[n0 + tx*8 + j];
#pragma unroll
    for (int i = 0; i < 8; i++) {
        int row = row0 + ty*8 + i;
        float* crow = C + (size_t)row*DD + n0 + tx*8;
        float4 o0, o1;
        o0.x = acc2[i][0].x+bj[0]; o0.y = acc2[i][0].y+bj[1];
        o0.z = acc2[i][1].x+bj[2]; o0.w = acc2[i][1].y+bj[3];
        o1.x = acc2[i][2].x+bj[4]; o1.y = acc2[i][2].y+bj[5];
        o1.z = acc2[i][3].x+bj[6]; o1.w = acc2[i][3].y+bj[7];
        *(float4*)crow       = o0;
        *(float4*)(crow + 4) = o1;
    }
}

// ---------------- fused voh (blocks 0..767) + scores (blocks 768..1279) ----------------
struct SmemVoh { float2 As2[32][128]; float2 Ws2[32][64]; };
struct SmemSc  { float qh[32][48]; float kh[32][96]; };

__global__ __launch_bounds__(256) void k_vs(const float* __restrict__ W1, const float* __restrict__ W2) {
    __shared__ union { SmemVoh v; SmemSc s; } sm;
    int bx = blockIdx.x;
    int tid = threadIdx.x;

    if (bx < 768) {
        int x = bx % 24, rest = bx / 24;
        int y = rest & 1, z = rest >> 1;
        int set = z >> 3, h = z & 7;
        const float* Wout = (set ? W2 : W1) + 3*DD*DD + h*DPH*DD;
        const float* V = g_v[set];
        int r0 = x * 128, n0 = y * 128;
        int tx = tid & 15, ty = tid >> 4;

        {
            int rr = tid >> 1, kq = (tid & 1) * 16;
            const float* ap = V + (size_t)(r0 + rr)*DD + h*DPH + kq;
#pragma unroll
            for (int c = 0; c < 4; c++) {
                float4 av = *(const float4*)(ap + c*4);
                sm.v.As2[kq + c*4 + 0][rr] = make_float2(av.x, av.x);
                sm.v.As2[kq + c*4 + 1][rr] = make_float2(av.y, av.y);
                sm.v.As2[kq + c*4 + 2][rr] = make_float2(av.z, av.z);
                sm.v.As2[kq + c*4 + 3][rr] = make_float2(av.w, av.w);
            }
        }
        {
            int wk = tid >> 5, wp = (tid & 31) * 2, wn = (tid & 31) * 4;
#pragma unroll
            for (int s = 0; s < 4; s++) {
                float4 wv = *(const float4*)(Wout + (size_t)(wk + 8*s)*DD + n0 + wn);
                sm.v.Ws2[wk + 8*s][wp]   = make_float2(wv.x, wv.y);
                sm.v.Ws2[wk + 8*s][wp+1] = make_float2(wv.z, wv.w);
            }
        }
        __syncthreads();

        float2 acc2[8][4];
#pragma unroll
        for (int i = 0; i < 8; i++)
#pragma unroll
            for (int j = 0; j < 4; j++) acc2[i][j] = make_float2(0.f, 0.f);

#pragma unroll
        for (int kk = 0; kk < 32; kk++) {
            float2 a[8], bfr[4];
#pragma unroll
            for (int i = 0; i < 8; i++) a[i] = sm.v.As2[kk][ty*8 + i];
#pragma unroll
            for (int j = 0; j < 4; j++) bfr[j] = sm.v.Ws2[kk][tx*4 + j];
#pragma unroll
            for (int i = 0; i < 8; i++)
#pragma unroll
                for (int j = 0; j < 4; j++) fma2(acc2[i][j], a[i], bfr[j]);
        }

#pragma unroll
        for (int i = 0; i < 8; i++) {
            int row = r0 + ty*8 + i;
            float* op = g_voh[set] + ((size_t)row*HH + h)*DD + n0 + tx*8;
            float4 o0, o1;
            o0.x = acc2[i][0].x; o0.y = acc2[i][0].y; o0.z = acc2[i][1].x; o0.w = acc2[i][1].y;
            o1.x = acc2[i][2].x; o1.y = acc2[i][2].y; o1.z = acc2[i][3].x; o1.w = acc2[i][3].y;
            *(float4*)op       = o0;
            *(float4*)(op + 4) = o1;
        }
    } else {
        int id = bx - 768;
        int h = id & 7, b = (id >> 3) & 31, set = id >> 8;

        for (int i = tid; i < EE*DPH; i += 256) {
            int q = i >> 5, d = i & 31;
            sm.s.qh[d][q] = g_qp[set][(b*EE + q)*DD + h*DPH + d];
        }
        for (int i = tid; i < MM*DPH; i += 256) {
            int m = i >> 5, d = i & 31;
            sm.s.kh[d][m] = g_kp[set][(b*MM + m)*DD + h*DPH + d];
        }
        __syncthreads();

        int q0 = (tid >> 4) * 3;
        int m0 = (tid & 15) * 6;
        float acc[3][6];
#pragma unroll
        for (int i = 0; i < 3; i++)
#pragma unroll
            for (int j = 0; j < 6; j++) acc[i][j] = 0.f;

#pragma unroll 8
        for (int kk = 0; kk < DPH; kk++) {
            float qv[3], kv[6];
#pragma unroll
            for (int i = 0; i < 3; i++) qv[i] = sm.s.qh[kk][q0 + i];
#pragma unroll
            for (int j = 0; j < 6; j++) kv[j] = sm.s.kh[kk][m0 + j];
#pragma unroll
            for (int i = 0; i < 3; i++)
#pragma unroll
                for (int j = 0; j < 6; j++) acc[i][j] += qv[i] * kv[j];
        }

        const float scale = 0.17677669529663687f;
#pragma unroll
        for (int i = 0; i < 3; i++) {
            float* sp = &g_sc[set][((size_t)(b*EE + q0 + i)*HH + h)*MM + m0];
#pragma unroll
            for (int j = 0; j < 6; j++) sp[j] = acc[i][j] * scale;
        }
    }
}

// fused single-pass LayerNorm + write; gamma/beta passed in (hoisted)
__device__ __forceinline__ void ln_write(
    float* x, float4 gm0, float4 gm1, float4 bt0, float4 bt1,
    float* op, int d0, int d1)
{
    float sm = 0.f, s2 = 0.f;
#pragma unroll
    for (int j = 0; j < 8; j++) { sm += x[j]; s2 += x[j]*x[j]; }
#pragma unroll
    for (int o = 16; o > 0; o >>= 1) {
        sm += __shfl_xor_sync(0xffffffffu, sm, o);
        s2 += __shfl_xor_sync(0xffffffffu, s2, o);
    }
    float mu  = sm * (1.f/DD);
    float var = fmaxf(s2 * (1.f/DD) - mu*mu, 0.f);
    float rs  = rsqrtf(var + 1e-5f);

    float4 o0, o1;
    o0.x = (x[0]-mu)*rs*gm0.x + bt0.x; o0.y = (x[1]-mu)*rs*gm0.y + bt0.y;
    o0.z = (x[2]-mu)*rs*gm0.z + bt0.z; o0.w = (x[3]-mu)*rs*gm0.w + bt0.w;
    o1.x = (x[4]-mu)*rs*gm1.x + bt1.x; o1.y = (x[5]-mu)*rs*gm1.y + bt1.y;
    o1.z = (x[6]-mu)*rs*gm1.z + bt1.z; o1.w = (x[7]-mu)*rs*gm1.w + bt1.w;
    *(float4*)(op + d0) = o0;
    *(float4*)(op + d1) = o1;
}

// ---------------- combine v7: 6 q per warp (all 48 q per block), grid (48,32,2) ----------------
__shared__ int   s_ml[MAXML];
__shared__ float s_al[SCAP][EE*HH];   // 12 KB
__shared__ float s_mx[EE*HH];
__shared__ float s_is[EE*HH];

// accumulate n mentions (alphas in s_al[0..n-1]) into acc2[6][4]
__device__ __forceinline__ void accum_chunk(
    float2 acc2[6][4], const float* __restrict__ vohb,
    int base, int n, int wid, int d0, int d1)
{
    for (int i = 0; i < n; i++) {
        const float* vrow = vohb + (size_t)s_ml[base + i]*(HH*DD);
        const float* arow = s_al[i];
#pragma unroll
        for (int hp = 0; hp < 4; hp++) {          // head pairs
            float2 a2[6];
#pragma unroll
            for (int t = 0; t < 6; t++)
                a2[t] = *(const float2*)&arow[(wid + 8*t)*8 + hp*2];
#pragma unroll
            for (int hh = 0; hh < 2; hh++) {
                const float* vp = vrow + (hp*2 + hh)*DD;
                float4 v0 = ldg4(vp + d0);
                float4 v1 = ldg4(vp + d1);
                float2 v0a = make_float2(v0.x, v0.y), v0b = make_float2(v0.z, v0.w);
                float2 v1a = make_float2(v1.x, v1.y), v1b = make_float2(v1.z, v1.w);
#pragma unroll
                for (int t = 0; t < 6; t++) {
                    float av = hh ? a2[t].y : a2[t].x;
                    float2 aa = make_float2(av, av);
                    fma2(acc2[t][0], aa, v0a);
                    fma2(acc2[t][1], aa, v0b);
                    fma2(acc2[t][2], aa, v1a);
                    fma2(acc2[t][3], aa, v1b);
                }
            }
        }
    }
}

__global__ __launch_bounds__(256, 3) void k_combine(
    const float* __restrict__ ent,
    const float* __restrict__ b1, const float* __restrict__ ln1,
    const float* __restrict__ b2, const float* __restrict__ ln2,
    float* __restrict__ out)
{
    int e = blockIdx.x, b = blockIdx.y, set = blockIdx.z;
    int tid = threadIdx.x, lane = tid & 31, wid = tid >> 5;

    int cnt = g_mcnt[b*EE + e];
    if (tid < MAXML) s_ml[tid] = (tid < cnt) ? g_mlist[(b*EE + e)*MAXML + tid] : 0;
    __syncthreads();

    const float* vohb = g_voh[set] + (size_t)b*MM*HH*DD;
    const float* bbp  = (set ? b2 : b1) + 3*DD;
    const float* ln   = (set ? ln2 : ln1);
    int d0 = lane*4, d1 = 128 + lane*4;
    size_t outb = ((size_t)set*BB + b) * PAIRS * DD;

    if (cnt == 1) {
        const float* vrow = vohb + (size_t)s_ml[0]*(HH*DD);
        float4 bo0 = ldg4(bbp + d0), bo1 = ldg4(bbp + d1);
        float s[8];
        s[0]=bo0.x; s[1]=bo0.y; s[2]=bo0.z; s[3]=bo0.w;
        s[4]=bo1.x; s[5]=bo1.y; s[6]=bo1.z; s[7]=bo1.w;
#pragma unroll
        for (int h = 0; h < HH; h++) {
            float4 v0 = ldg4(vrow + h*DD + d0);
            float4 v1 = ldg4(vrow + h*DD + d1);
            s[0]+=v0.x; s[1]+=v0.y; s[2]+=v0.z; s[3]+=v0.w;
            s[4]+=v1.x; s[5]+=v1.y; s[6]+=v1.z; s[7]+=v1.w;
        }
        float4 gm0 = ldg4(ln + d0),      gm1 = ldg4(ln + d1);
        float4 bt0 = ldg4(ln + DD + d0), bt1 = ldg4(ln + DD + d1);
#pragma unroll
        for (int t = 0; t < 6; t++) {
            int q = wid + 8*t;
            const float* er = ent + (size_t)(b*EE + q)*DD;
            float4 e0 = ldg4(er + d0), e1 = ldg4(er + d1);
            float x[8];
            x[0]=s[0]+e0.x; x[1]=s[1]+e0.y; x[2]=s[2]+e0.z; x[3]=s[3]+e0.w;
            x[4]=s[4]+e1.x; x[5]=s[5]+e1.y; x[6]=s[6]+e1.z; x[7]=s[7]+e1.w;
            int orow = set ? (q*EE + e) : (e*EE + q);
            ln_write(x, gm0, gm1, bt0, bt1, out + outb + (size_t)orow*DD, d0, d1);
        }
        return;
    }

    const float* scb = g_sc[set] + (size_t)b*EE*HH*MM;

    float2 acc2[6][4];
#pragma unroll
    for (int t = 0; t < 6; t++)
#pragma unroll
        for (int j = 0; j < 4; j++) acc2[t][j] = make_float2(0.f, 0.f);

    if (cnt <= SCAP) {
        for (int t = tid; t < EE*HH; t += 256) {
            int lq = t >> 3, h = t & 7;
            const float* sp = scb + ((size_t)lq*HH + h)*MM;
            float sv[SCAP];
            float mx = -1e30f;
            for (int i = 0; i < cnt; i++) { sv[i] = sp[s_ml[i]]; mx = fmaxf(mx, sv[i]); }
            float s = 0.f;
            for (int i = 0; i < cnt; i++) { sv[i] = __expf(sv[i] - mx); s += sv[i]; }
            float inv = 1.f / s;
            for (int i = 0; i < cnt; i++) s_al[i][t] = sv[i] * inv;
        }
        __syncthreads();
        accum_chunk(acc2, vohb, 0, cnt, wid, d0, d1);
    } else {
        for (int t = tid; t < EE*HH; t += 256) {
            int lq = t >> 3, h = t & 7;
            const float* sp = scb + ((size_t)lq*HH + h)*MM;
            float mx = -1e30f;
            for (int i = 0; i < cnt; i++) mx = fmaxf(mx, sp[s_ml[i]]);
            float s = 0.f;
            for (int i = 0; i < cnt; i++) s += __expf(sp[s_ml[i]] - mx);
            s_mx[t] = mx; s_is[t] = 1.f / s;
        }
        __syncthreads();
        for (int base = 0; base < cnt; base += SCAP) {
            int n = min(SCAP, cnt - base);
            for (int idx = tid; idx < EE*HH*n; idx += 256) {
                int i = idx / (EE*HH), t = idx - i*(EE*HH);
                int lq = t >> 3, h = t & 7;
                float sv = scb[((size_t)lq*HH + h)*MM + s_ml[base + i]];
                s_al[i][t] = __expf(sv - s_mx[t]) * s_is[t];
            }
            __syncthreads();
            accum_chunk(acc2, vohb, base, n, wid, d0, d1);
            __syncthreads();
        }
    }

    float4 bo0 = ldg4(bbp + d0), bo1 = ldg4(bbp + d1);
    float4 gm0 = ldg4(ln + d0),      gm1 = ldg4(ln + d1);
    float4 bt0 = ldg4(ln + DD + d0), bt1 = ldg4(ln + DD + d1);
#pragma unroll
    for (int t = 0; t < 6; t++) {
        int q = wid + 8*t;
        const float* er = ent + (size_t)(b*EE + q)*DD;
        float4 e0 = ldg4(er + d0), e1 = ldg4(er + d1);
        float x[8];
        x[0] = acc2[t][0].x + bo0.x + e0.x; x[1] = acc2[t][0].y + bo0.y + e0.y;
        x[2] = acc2[t][1].x + bo0.z + e0.z; x[3] = acc2[t][1].y + bo0.w + e0.w;
        x[4] = acc2[t][2].x + bo1.x + e1.x; x[5] = acc2[t][2].y + bo1.y + e1.y;
        x[6] = acc2[t][3].x + bo1.z + e1.z; x[7] = acc2[t][3].y + bo1.w + e1.w;
        int orow = set ? (q*EE + e) : (e*EE + q);
        ln_write(x, gm0, gm1, bt0, bt1, out + outb + (size_t)orow*DD, d0, d1);
    }
}

// ---------------- launch ----------------
extern "C" void kernel_launch(void* const* d_in, const int* in_sizes, int n_in,
                              void* d_out, int out_size) {
    const void*  info = d_in[0];
    const float* ent  = (const float*)d_in[2];
    const float* men  = (const float*)d_in[3];
    const float* sen  = (const float*)d_in[4];
    const float* W1   = (const float*)d_in[5];
    const float* b1   = (const float*)d_in[6];
    const float* ln1  = (const float*)d_in[7];
    const float* W2   = (const float*)d_in[8];
    const float* b2   = (const float*)d_in[9];
    const float* ln2  = (const float*)d_in[10];
    float* out = (float*)d_out;

    k_prep<<<BB, 128>>>(info);
    k_proj_all<<<240, 256>>>(ent, men, sen, W1, b1, W2, b2);
    k_vs<<<1280, 256>>>(W1, W2);
    k_combine<<<dim3(EE, BB, 2), 256>>>(ent, b1, ln1, b2, ln2, out);
}

// round 12
// speedup vs baseline: 1.0947x; 1.0947x over previous
#include <cuda_runtime.h>

#define BB   32
#define EE   48
#define MM   96
#define DD   256
#define HH   8
#define DPH  32
#define PAIRS (EE*EE)
#define MAXML 64
#define SCAP 8
#define QH   24   // q rows per combine block (half of EE)

// ---------------- scratch ----------------
__device__ int   g_sidx[BB*MM];
__device__ int   g_mlist[BB*EE*MAXML];
__device__ int   g_mcnt [BB*EE];
__device__ float g_qp [2][BB*EE*DD];
__device__ float g_kp [2][BB*MM*DD];
__device__ float g_v  [2][BB*MM*DD];
__device__ float g_voh[2][BB*MM*HH*DD];
__device__ float g_sc [2][BB*EE*HH*MM];

__device__ __forceinline__ void fma2(float2& d, float2 a, float2 b) {
    unsigned long long dd = *(unsigned long long*)&d;
    unsigned long long aa = *(unsigned long long*)&a;
    unsigned long long bb = *(unsigned long long*)&b;
    asm("fma.rn.f32x2 %0, %1, %2, %0;" : "+l"(dd) : "l"(aa), "l"(bb));
    d = *(float2*)&dd;
}

__device__ __forceinline__ float4 ldg4(const float* p) {
    return __ldg((const float4*)p);
}

// ---------------- prep: one block per doc ----------------
__global__ void k_prep(const void* info) {
    int b = blockIdx.x, tid = threadIdx.x;
    __shared__ int smid[MM];
    __shared__ int s[128];
    const int* p32 = (const int*)info;
    int mx = 0;
    for (int r = tid; r < BB*MM; r += 128) mx = max(mx, p32[r*6 + 4]);
    s[tid] = mx; __syncthreads();
    for (int o = 64; o > 0; o >>= 1) { if (tid < o) s[tid] = max(s[tid], s[tid+o]); __syncthreads(); }
    int is32 = (s[0] > 0);
    for (int m = tid; m < MM; m += 128) {
        int r = b*MM + m;
        int e, sidx;
        if (is32) { e = p32[r*6 + 0]; sidx = p32[r*6 + 4]; }
        else {
            const long long* p64 = (const long long*)info;
            e = (int)p64[r*6 + 0]; sidx = (int)p64[r*6 + 4];
        }
        smid[m] = e; g_sidx[r] = sidx;
    }
    __syncthreads();
    for (int e = tid; e < EE; e += 128) {
        int target = b*EE + e;
        int cnt = 0;
        for (int m = 0; m < MM; m++) {
            if (smid[m] == target && cnt < MAXML)
                g_mlist[target*MAXML + cnt++] = m;
        }
        g_mcnt[target] = cnt;
    }
}

// ---------------- all 6 projections: 128x128 tiles, KSTEP=16, f32x2 ----------------
__global__ __launch_bounds__(256, 2) void k_proj_all(
    const float* __restrict__ ent, const float* __restrict__ men, const float* __restrict__ sen,
    const float* __restrict__ W1, const float* __restrict__ b1,
    const float* __restrict__ W2, const float* __restrict__ b2)
{
    __shared__ float2 As2[16][128];
    __shared__ float2 Ws2[16][64];

    int blk = blockIdx.x;
    int cb = blk & 1, rb = blk >> 1;
    int set = rb / 60; int r = rb % 60;
    const float* A; int gather = 0, type, row0;
    if (r < 12)      { type = 0; row0 = r*128;      A = ent; }
    else if (r < 36) { type = 1; row0 = (r-12)*128; A = sen; gather = 1; }
    else             { type = 2; row0 = (r-36)*128; A = men; }
    const float* W  = (set ? W2 : W1) + type*DD*DD;
    const float* bi = (set ? b2 : b1) + type*DD;
    float* C = (type == 0) ? g_qp[set] : (type == 1 ? g_kp[set] : g_v[set]);
    int n0 = cb*128;

    int tid = threadIdx.x;
    int tx = tid & 15, ty = tid >> 4;

    int am  = tid >> 1;
    int akq = (tid & 1) * 8;
    int arow = row0 + am;
    int asrc = gather ? g_sidx[arow] : arow;
    const float* aptr = A + (size_t)asrc*DD + akq;
    int wk = tid >> 4;
    int wn = (tid & 15) * 8;
    const float* wptr = W + (size_t)wk*DD + n0 + wn;
    int wp = (tid & 15) * 4;

    float2 acc2[8][4];
#pragma unroll
    for (int i = 0; i < 8; i++)
#pragma unroll
        for (int j = 0; j < 4; j++) acc2[i][j] = make_float2(0.f, 0.f);

    for (int k0 = 0; k0 < DD; k0 += 16) {
        float4 a0 = *(const float4*)(aptr + k0);
        float4 a1 = *(const float4*)(aptr + k0 + 4);
        float4 w0 = *(const float4*)(wptr + (size_t)k0*DD);
        float4 w1 = *(const float4*)(wptr + (size_t)k0*DD + 4);
        As2[akq+0][am] = make_float2(a0.x, a0.x);
        As2[akq+1][am] = make_float2(a0.y, a0.y);
        As2[akq+2][am] = make_float2(a0.z, a0.z);
        As2[akq+3][am] = make_float2(a0.w, a0.w);
        As2[akq+4][am] = make_float2(a1.x, a1.x);
        As2[akq+5][am] = make_float2(a1.y, a1.y);
        As2[akq+6][am] = make_float2(a1.z, a1.z);
        As2[akq+7][am] = make_float2(a1.w, a1.w);
        Ws2[wk][wp]   = make_float2(w0.x, w0.y);
        Ws2[wk][wp+1] = make_float2(w0.z, w0.w);
        Ws2[wk][wp+2] = make_float2(w1.x, w1.y);
        Ws2[wk][wp+3] = make_float2(w1.z, w1.w);
        __syncthreads();
#pragma unroll
        for (int kk = 0; kk < 16; kk++) {
            float2 a[8], bfr[4];
#pragma unroll
            for (int i = 0; i < 8; i++) a[i] = As2[kk][ty*8 + i];
#pragma unroll
            for (int j = 0; j < 4; j++) bfr[j] = Ws2[kk][tx*4 + j];
#pragma unroll
            for (int i = 0; i < 8; i++)
#pragma unroll
                for (int j = 0; j < 4; j++) fma2(acc2[i][j], a[i], bfr[j]);
        }
        __syncthreads();
    }

    float bj[8];
#pragma unroll
    for (int j = 0; j < 8; j++) bj[j] = bi[n0 + tx*8 + j];
#pragma unroll
    for (int i = 0; i < 8; i++) {
        int row = row0 + ty*8 + i;
        float* crow = C + (size_t)row*DD + n0 + tx*8;
        float4 o0, o1;
        o0.x = acc2[i][0].x+bj[0]; o0.y = acc2[i][0].y+bj[1];
        o0.z = acc2[i][1].x+bj[2]; o0.w = acc2[i][1].y+bj[3];
        o1.x = acc2[i][2].x+bj[4]; o1.y = acc2[i][2].y+bj[5];
        o1.z = acc2[i][3].x+bj[6]; o1.w = acc2[i][3].y+bj[7];
        *(float4*)crow       = o0;
        *(float4*)(crow + 4) = o1;
    }
}

// ---------------- fused voh (blocks 0..767) + scores (blocks 768..1279) ----------------
struct SmemVoh { float2 As2[32][128]; float2 Ws2[32][64]; };
struct SmemSc  { float qh[32][48]; float kh[32][96]; };

__global__ __launch_bounds__(256) void k_vs(const float* __restrict__ W1, const float* __restrict__ W2) {
    __shared__ union { SmemVoh v; SmemSc s; } sm;
    int bx = blockIdx.x;
    int tid = threadIdx.x;

    if (bx < 768) {
        int x = bx % 24, rest = bx / 24;
        int y = rest & 1, z = rest >> 1;
        int set = z >> 3, h = z & 7;
        const float* Wout = (set ? W2 : W1) + 3*DD*DD + h*DPH*DD;
        const float* V = g_v[set];
        int r0 = x * 128, n0 = y * 128;
        int tx = tid & 15, ty = tid >> 4;

        {
            int rr = tid >> 1, kq = (tid & 1) * 16;
            const float* ap = V + (size_t)(r0 + rr)*DD + h*DPH + kq;
#pragma unroll
            for (int c = 0; c < 4; c++) {
                float4 av = *(const float4*)(ap + c*4);
                sm.v.As2[kq + c*4 + 0][rr] = make_float2(av.x, av.x);
                sm.v.As2[kq + c*4 + 1][rr] = make_float2(av.y, av.y);
                sm.v.As2[kq + c*4 + 2][rr] = make_float2(av.z, av.z);
                sm.v.As2[kq + c*4 + 3][rr] = make_float2(av.w, av.w);
            }
        }
        {
            int wk = tid >> 5, wp = (tid & 31) * 2, wn = (tid & 31) * 4;
#pragma unroll
            for (int s = 0; s < 4; s++) {
                float4 wv = *(const float4*)(Wout + (size_t)(wk + 8*s)*DD + n0 + wn);
                sm.v.Ws2[wk + 8*s][wp]   = make_float2(wv.x, wv.y);
                sm.v.Ws2[wk + 8*s][wp+1] = make_float2(wv.z, wv.w);
            }
        }
        __syncthreads();

        float2 acc2[8][4];
#pragma unroll
        for (int i = 0; i < 8; i++)
#pragma unroll
            for (int j = 0; j < 4; j++) acc2[i][j] = make_float2(0.f, 0.f);

#pragma unroll
        for (int kk = 0; kk < 32; kk++) {
            float2 a[8], bfr[4];
#pragma unroll
            for (int i = 0; i < 8; i++) a[i] = sm.v.As2[kk][ty*8 + i];
#pragma unroll
            for (int j = 0; j < 4; j++) bfr[j] = sm.v.Ws2[kk][tx*4 + j];
#pragma unroll
            for (int i = 0; i < 8; i++)
#pragma unroll
                for (int j = 0; j < 4; j++) fma2(acc2[i][j], a[i], bfr[j]);
        }

#pragma unroll
        for (int i = 0; i < 8; i++) {
            int row = r0 + ty*8 + i;
            float* op = g_voh[set] + ((size_t)row*HH + h)*DD + n0 + tx*8;
            float4 o0, o1;
            o0.x = acc2[i][0].x; o0.y = acc2[i][0].y; o0.z = acc2[i][1].x; o0.w = acc2[i][1].y;
            o1.x = acc2[i][2].x; o1.y = acc2[i][2].y; o1.z = acc2[i][3].x; o1.w = acc2[i][3].y;
            *(float4*)op       = o0;
            *(float4*)(op + 4) = o1;
        }
    } else {
        int id = bx - 768;
        int h = id & 7, b = (id >> 3) & 31, set = id >> 8;

        for (int i = tid; i < EE*DPH; i += 256) {
            int q = i >> 5, d = i & 31;
            sm.s.qh[d][q] = g_qp[set][(b*EE + q)*DD + h*DPH + d];
        }
        for (int i = tid; i < MM*DPH; i += 256) {
            int m = i >> 5, d = i & 31;
            sm.s.kh[d][m] = g_kp[set][(b*MM + m)*DD + h*DPH + d];
        }
        __syncthreads();

        int q0 = (tid >> 4) * 3;
        int m0 = (tid & 15) * 6;
        float acc[3][6];
#pragma unroll
        for (int i = 0; i < 3; i++)
#pragma unroll
            for (int j = 0; j < 6; j++) acc[i][j] = 0.f;

#pragma unroll 8
        for (int kk = 0; kk < DPH; kk++) {
            float qv[3], kv[6];
#pragma unroll
            for (int i = 0; i < 3; i++) qv[i] = sm.s.qh[kk][q0 + i];
#pragma unroll
            for (int j = 0; j < 6; j++) kv[j] = sm.s.kh[kk][m0 + j];
#pragma unroll
            for (int i = 0; i < 3; i++)
#pragma unroll
                for (int j = 0; j < 6; j++) acc[i][j] += qv[i] * kv[j];
        }

        const float scale = 0.17677669529663687f;
#pragma unroll
        for (int i = 0; i < 3; i++) {
            float* sp = &g_sc[set][((size_t)(b*EE + q0 + i)*HH + h)*MM + m0];
#pragma unroll
            for (int j = 0; j < 6; j++) sp[j] = acc[i][j] * scale;
        }
    }
}

// ---------------- combine v8: 4 q-groups x 2 d-halves, 6q x 128d per warp ----------------
__shared__ int    s_ml[MAXML];
__shared__ float  s_al[SCAP][QH*HH];   // 6 KB
__shared__ float  s_mx[QH*HH];
__shared__ float  s_is[QH*HH];
__shared__ float2 s_par[QH][2];        // per-q partial (sum, sumsq) per d-half

// accumulate n mentions (alphas in s_al[0..n-1]) into acc2[6][2]; warp covers 128 d at dbase
__device__ __forceinline__ void accum_chunk(
    float2 acc2[6][2], const float* __restrict__ vohb,
    int base, int n, int qg, int dbase)
{
    for (int i = 0; i < n; i++) {
        const float* vrow = vohb + (size_t)s_ml[base + i]*(HH*DD) + dbase;
        const float* arow = s_al[i] + qg*6*8;
#pragma unroll
        for (int hp = 0; hp < 4; hp++) {          // head pairs
            float2 a2[6];
#pragma unroll
            for (int t = 0; t < 6; t++)
                a2[t] = *(const float2*)&arow[t*8 + hp*2];
#pragma unroll
            for (int hh = 0; hh < 2; hh++) {
                float4 v = ldg4(vrow + (hp*2 + hh)*DD);
                float2 va = make_float2(v.x, v.y), vb = make_float2(v.z, v.w);
#pragma unroll
                for (int t = 0; t < 6; t++) {
                    float av = hh ? a2[t].y : a2[t].x;
                    float2 aa = make_float2(av, av);
                    fma2(acc2[t][0], aa, va);
                    fma2(acc2[t][1], aa, vb);
                }
            }
        }
    }
}

__global__ __launch_bounds__(256, 4) void k_combine(
    const float* __restrict__ ent,
    const float* __restrict__ b1, const float* __restrict__ ln1,
    const float* __restrict__ b2, const float* __restrict__ ln2,
    float* __restrict__ out)
{
    int e = blockIdx.x, b = blockIdx.y, z = blockIdx.z;
    int set = z >> 1, half = z & 1;
    int q0 = half * QH;
    int tid = threadIdx.x, lane = tid & 31, wid = tid >> 5;
    int qg = wid >> 1;            // 0..3: q-group (6 q each)
    int dh = wid & 1;             // 0..1: d-half
    int dbase = dh*128 + lane*4;  // 4 floats per thread

    int cnt = g_mcnt[b*EE + e];
    if (tid < MAXML) s_ml[tid] = (tid < cnt) ? g_mlist[(b*EE + e)*MAXML + tid] : 0;
    __syncthreads();

    const float* vohb = g_voh[set] + (size_t)b*MM*HH*DD;
    const float* bbp  = (set ? b2 : b1) + 3*DD;
    const float* ln   = (set ? ln2 : ln1);
    size_t outb = ((size_t)set*BB + b) * PAIRS * DD;

    float4 bo = ldg4(bbp + dbase);
    float x[6][4];

    if (cnt == 1) {
        const float* vrow = vohb + (size_t)s_ml[0]*(HH*DD) + dbase;
        float s0 = bo.x, s1 = bo.y, s2v = bo.z, s3 = bo.w;
#pragma unroll
        for (int h = 0; h < HH; h++) {
            float4 v = ldg4(vrow + h*DD);
            s0 += v.x; s1 += v.y; s2v += v.z; s3 += v.w;
        }
#pragma unroll
        for (int t = 0; t < 6; t++) {
            int q = q0 + qg*6 + t;
            float4 e0 = ldg4(ent + (size_t)(b*EE + q)*DD + dbase);
            x[t][0] = s0 + e0.x; x[t][1] = s1 + e0.y;
            x[t][2] = s2v + e0.z; x[t][3] = s3 + e0.w;
        }
    } else {
        const float* scb = g_sc[set] + ((size_t)b*EE + q0)*HH*MM;

        float2 acc2[6][2];
#pragma unroll
        for (int t = 0; t < 6; t++) {
            acc2[t][0] = make_float2(0.f, 0.f);
            acc2[t][1] = make_float2(0.f, 0.f);
        }

        if (cnt <= SCAP) {
            for (int t = tid; t < QH*HH; t += 256) {
                const float* sp = scb + (size_t)t*MM;   // t = lq*8+h matches layout
                float sv[SCAP];
                float mx = -1e30f;
                for (int i = 0; i < cnt; i++) { sv[i] = sp[s_ml[i]]; mx = fmaxf(mx, sv[i]); }
                float s = 0.f;
                for (int i = 0; i < cnt; i++) { sv[i] = __expf(sv[i] - mx); s += sv[i]; }
                float inv = 1.f / s;
                for (int i = 0; i < cnt; i++) s_al[i][t] = sv[i] * inv;
            }
            __syncthreads();
            accum_chunk(acc2, vohb, 0, cnt, qg, dbase);
        } else {
            for (int t = tid; t < QH*HH; t += 256) {
                const float* sp = scb + (size_t)t*MM;
                float mx = -1e30f;
                for (int i = 0; i < cnt; i++) mx = fmaxf(mx, sp[s_ml[i]]);
                float s = 0.f;
                for (int i = 0; i < cnt; i++) s += __expf(sp[s_ml[i]] - mx);
                s_mx[t] = mx; s_is[t] = 1.f / s;
            }
            __syncthreads();
            for (int base = 0; base < cnt; base += SCAP) {
                int n = min(SCAP, cnt - base);
                for (int idx = tid; idx < QH*HH*n; idx += 256) {
                    int i = idx / (QH*HH), t = idx - i*(QH*HH);
                    float sv = scb[(size_t)t*MM + s_ml[base + i]];
                    s_al[i][t] = __expf(sv - s_mx[t]) * s_is[t];
                }
                __syncthreads();
                accum_chunk(acc2, vohb, base, n, qg, dbase);
                __syncthreads();
            }
        }

#pragma unroll
        for (int t = 0; t < 6; t++) {
            int q = q0 + qg*6 + t;
            float4 e0 = ldg4(ent + (size_t)(b*EE + q)*DD + dbase);
            x[t][0] = acc2[t][0].x + bo.x + e0.x;
            x[t][1] = acc2[t][0].y + bo.y + e0.y;
            x[t][2] = acc2[t][1].x + bo.z + e0.z;
            x[t][3] = acc2[t][1].y + bo.w + e0.w;
        }
    }

    // per-q partial (sum, sumsq) over this warp's 128 columns
#pragma unroll
    for (int t = 0; t < 6; t++) {
        float sm = x[t][0] + x[t][1] + x[t][2] + x[t][3];
        float s2 = x[t][0]*x[t][0] + x[t][1]*x[t][1] + x[t][2]*x[t][2] + x[t][3]*x[t][3];
#pragma unroll
        for (int o = 16; o > 0; o >>= 1) {
            sm += __shfl_xor_sync(0xffffffffu, sm, o);
            s2 += __shfl_xor_sync(0xffffffffu, s2, o);
        }
        if (lane == 0) s_par[qg*6 + t][dh] = make_float2(sm, s2);
    }
    __syncthreads();

    float4 gm = ldg4(ln + dbase);
    float4 bt = ldg4(ln + DD + dbase);
#pragma unroll
    for (int t = 0; t < 6; t++) {
        int lq = qg*6 + t;
        float2 p0 = s_par[lq][0], p1 = s_par[lq][1];
        float mu  = (p0.x + p1.x) * (1.f/DD);
        float var = fmaxf((p0.y + p1.y) * (1.f/DD) - mu*mu, 0.f);
        float rs  = rsqrtf(var + 1e-5f);
        int q = q0 + lq;
        int orow = set ? (q*EE + e) : (e*EE + q);
        float4 o;
        o.x = (x[t][0]-mu)*rs*gm.x + bt.x;
        o.y = (x[t][1]-mu)*rs*gm.y + bt.y;
        o.z = (x[t][2]-mu)*rs*gm.z + bt.z;
        o.w = (x[t][3]-mu)*rs*gm.w + bt.w;
        *(float4*)(out + outb + (size_t)orow*DD + dbase) = o;
    }
}

// ---------------- launch ----------------
extern "C" void kernel_launch(void* const* d_in, const int* in_sizes, int n_in,
                              void* d_out, int out_size) {
    const void*  info = d_in[0];
    const float* ent  = (const float*)d_in[2];
    const float* men  = (const float*)d_in[3];
    const float* sen  = (const float*)d_in[4];
    const float* W1   = (const float*)d_in[5];
    const float* b1   = (const float*)d_in[6];
    const float* ln1  = (const float*)d_in[7];
    const float* W2   = (const float*)d_in[8];
    const float* b2   = (const float*)d_in[9];
    const float* ln2  = (const float*)d_in[10];
    float* out = (float*)d_out;

    k_prep<<<BB, 128>>>(info);
    k_proj_all<<<240, 256>>>(ent, men, sen, W1, b1, W2, b2);
    k_vs<<<1280, 256>>>(W1, W2);
    k_combine<<<dim3(EE, BB, 4), 256>>>(ent, b1, ln1, b2, ln2, out);
}

// round 13
// speedup vs baseline: 1.1102x; 1.0141x over previous
#include <cuda_runtime.h>

#define BB   32
#define EE   48
#define MM   96
#define SS   48
#define DD   256
#define HH   8
#define DPH  32
#define PAIRS (EE*EE)
#define MAXML 64
#define SCAP 8
#define QH   24   // q rows per combine block

// ---------------- scratch ----------------
__device__ int   g_sidx[BB*MM];
__device__ int   g_mlist[BB*EE*MAXML];
__device__ int   g_mcnt [BB*EE];
__device__ float g_qp [2][BB*EE*DD];
__device__ float g_kp [2][BB*SS*DD];      // projected SENTENCES (deduped)
__device__ float g_v  [2][BB*MM*DD];
__device__ float g_voh[2][BB*MM*HH*DD];
__device__ float g_sc [2][BB*EE*HH*MM];

__device__ __forceinline__ void fma2(float2& d, float2 a, float2 b) {
    unsigned long long dd = *(unsigned long long*)&d;
    unsigned long long aa = *(unsigned long long*)&a;
    unsigned long long bb = *(unsigned long long*)&b;
    asm("fma.rn.f32x2 %0, %1, %2, %0;" : "+l"(dd) : "l"(aa), "l"(bb));
    d = *(float2*)&dd;
}

__device__ __forceinline__ float4 ldg4(const float* p) { return __ldg((const float4*)p); }
__device__ __forceinline__ float2 ldg2(const float* p) { return __ldg((const float2*)p); }

// ---------------- prep: one block per doc ----------------
__global__ void k_prep(const void* info) {
    int b = blockIdx.x, tid = threadIdx.x;
    __shared__ int smid[MM];
    __shared__ int s[128];
    const int* p32 = (const int*)info;
    int mx = 0;
    for (int r = tid; r < BB*MM; r += 128) mx = max(mx, p32[r*6 + 4]);
    s[tid] = mx; __syncthreads();
    for (int o = 64; o > 0; o >>= 1) { if (tid < o) s[tid] = max(s[tid], s[tid+o]); __syncthreads(); }
    int is32 = (s[0] > 0);
    for (int m = tid; m < MM; m += 128) {
        int r = b*MM + m;
        int e, sidx;
        if (is32) { e = p32[r*6 + 0]; sidx = p32[r*6 + 4]; }
        else {
            const long long* p64 = (const long long*)info;
            e = (int)p64[r*6 + 0]; sidx = (int)p64[r*6 + 4];
        }
        smid[m] = e; g_sidx[r] = sidx;
    }
    __syncthreads();
    for (int e = tid; e < EE; e += 128) {
        int target = b*EE + e;
        int cnt = 0;
        for (int m = 0; m < MM; m++) {
            if (smid[m] == target && cnt < MAXML)
                g_mlist[target*MAXML + cnt++] = m;
        }
        g_mcnt[target] = cnt;
    }
}

// ---------------- 6 projections (ent 12 / sen 12 / men 24 tiles per set): grid 192 ----------------
__global__ __launch_bounds__(256, 2) void k_proj_all(
    const float* __restrict__ ent, const float* __restrict__ men, const float* __restrict__ sen,
    const float* __restrict__ W1, const float* __restrict__ b1,
    const float* __restrict__ W2, const float* __restrict__ b2)
{
    __shared__ float2 As2[16][128];
    __shared__ float2 Ws2[16][64];

    int blk = blockIdx.x;
    int cb = blk & 1, rb = blk >> 1;
    int set = rb / 48; int r = rb % 48;
    const float* A; int type, row0;
    if (r < 12)      { type = 0; row0 = r*128;      A = ent; }
    else if (r < 24) { type = 1; row0 = (r-12)*128; A = sen; }
    else             { type = 2; row0 = (r-24)*128; A = men; }
    const float* W  = (set ? W2 : W1) + type*DD*DD;
    const float* bi = (set ? b2 : b1) + type*DD;
    float* C = (type == 0) ? g_qp[set] : (type == 1 ? g_kp[set] : g_v[set]);
    int n0 = cb*128;

    int tid = threadIdx.x;
    int tx = tid & 15, ty = tid >> 4;

    int am  = tid >> 1;
    int akq = (tid & 1) * 8;
    const float* aptr = A + (size_t)(row0 + am)*DD + akq;
    int wk = tid >> 4;
    int wn = (tid & 15) * 8;
    const float* wptr = W + (size_t)wk*DD + n0 + wn;
    int wp = (tid & 15) * 4;

    float2 acc2[8][4];
#pragma unroll
    for (int i = 0; i < 8; i++)
#pragma unroll
        for (int j = 0; j < 4; j++) acc2[i][j] = make_float2(0.f, 0.f);

    for (int k0 = 0; k0 < DD; k0 += 16) {
        float4 a0 = *(const float4*)(aptr + k0);
        float4 a1 = *(const float4*)(aptr + k0 + 4);
        float4 w0 = *(const float4*)(wptr + (size_t)k0*DD);
        float4 w1 = *(const float4*)(wptr + (size_t)k0*DD + 4);
        As2[akq+0][am] = make_float2(a0.x, a0.x);
        As2[akq+1][am] = make_float2(a0.y, a0.y);
        As2[akq+2][am] = make_float2(a0.z, a0.z);
        As2[akq+3][am] = make_float2(a0.w, a0.w);
        As2[akq+4][am] = make_float2(a1.x, a1.x);
        As2[akq+5][am] = make_float2(a1.y, a1.y);
        As2[akq+6][am] = make_float2(a1.z, a1.z);
        As2[akq+7][am] = make_float2(a1.w, a1.w);
        Ws2[wk][wp]   = make_float2(w0.x, w0.y);
        Ws2[wk][wp+1] = make_float2(w0.z, w0.w);
        Ws2[wk][wp+2] = make_float2(w1.x, w1.y);
        Ws2[wk][wp+3] = make_float2(w1.z, w1.w);
        __syncthreads();
#pragma unroll
        for (int kk = 0; kk < 16; kk++) {
            float2 a[8], bfr[4];
#pragma unroll
            for (int i = 0; i < 8; i++) a[i] = As2[kk][ty*8 + i];
#pragma unroll
            for (int j = 0; j < 4; j++) bfr[j] = Ws2[kk][tx*4 + j];
#pragma unroll
            for (int i = 0; i < 8; i++)
#pragma unroll
                for (int j = 0; j < 4; j++) fma2(acc2[i][j], a[i], bfr[j]);
        }
        __syncthreads();
    }

    float bj[8];
#pragma unroll
    for (int j = 0; j < 8; j++) bj[j] = bi[n0 + tx*8 + j];
#pragma unroll
    for (int i = 0; i < 8; i++) {
        int row = row0 + ty*8 + i;
        float* crow = C + (size_t)row*DD + n0 + tx*8;
        float4 o0, o1;
        o0.x = acc2[i][0].x+bj[0]; o0.y = acc2[i][0].y+bj[1];
        o0.z = acc2[i][1].x+bj[2]; o0.w = acc2[i][1].y+bj[3];
        o1.x = acc2[i][2].x+bj[4]; o1.y = acc2[i][2].y+bj[5];
        o1.z = acc2[i][3].x+bj[6]; o1.w = acc2[i][3].y+bj[7];
        *(float4*)crow       = o0;
        *(float4*)(crow + 4) = o1;
    }
}

// ---------------- fused voh (blocks 0..767) + scores (blocks 768..1279) ----------------
struct SmemVoh { float2 As2[32][128]; float2 Ws2[32][64]; };
struct SmemSc  { float qh[32][48]; float kh[32][96]; };

__global__ __launch_bounds__(256) void k_vs(const float* __restrict__ W1, const float* __restrict__ W2) {
    __shared__ union { SmemVoh v; SmemSc s; } sm;
    __shared__ int ssid[MM];
    int bx = blockIdx.x;
    int tid = threadIdx.x;

    if (bx < 768) {
        int x = bx % 24, rest = bx / 24;
        int y = rest & 1, z = rest >> 1;
        int set = z >> 3, h = z & 7;
        const float* Wout = (set ? W2 : W1) + 3*DD*DD + h*DPH*DD;
        const float* V = g_v[set];
        int r0 = x * 128, n0 = y * 128;
        int tx = tid & 15, ty = tid >> 4;

        {
            int rr = tid >> 1, kq = (tid & 1) * 16;
            const float* ap = V + (size_t)(r0 + rr)*DD + h*DPH + kq;
#pragma unroll
            for (int c = 0; c < 4; c++) {
                float4 av = *(const float4*)(ap + c*4);
                sm.v.As2[kq + c*4 + 0][rr] = make_float2(av.x, av.x);
                sm.v.As2[kq + c*4 + 1][rr] = make_float2(av.y, av.y);
                sm.v.As2[kq + c*4 + 2][rr] = make_float2(av.z, av.z);
                sm.v.As2[kq + c*4 + 3][rr] = make_float2(av.w, av.w);
            }
        }
        {
            int wk = tid >> 5, wp = (tid & 31) * 2, wn = (tid & 31) * 4;
#pragma unroll
            for (int s = 0; s < 4; s++) {
                float4 wv = *(const float4*)(Wout + (size_t)(wk + 8*s)*DD + n0 + wn);
                sm.v.Ws2[wk + 8*s][wp]   = make_float2(wv.x, wv.y);
                sm.v.Ws2[wk + 8*s][wp+1] = make_float2(wv.z, wv.w);
            }
        }
        __syncthreads();

        float2 acc2[8][4];
#pragma unroll
        for (int i = 0; i < 8; i++)
#pragma unroll
            for (int j = 0; j < 4; j++) acc2[i][j] = make_float2(0.f, 0.f);

#pragma unroll
        for (int kk = 0; kk < 32; kk++) {
            float2 a[8], bfr[4];
#pragma unroll
            for (int i = 0; i < 8; i++) a[i] = sm.v.As2[kk][ty*8 + i];
#pragma unroll
            for (int j = 0; j < 4; j++) bfr[j] = sm.v.Ws2[kk][tx*4 + j];
#pragma unroll
            for (int i = 0; i < 8; i++)
#pragma unroll
                for (int j = 0; j < 4; j++) fma2(acc2[i][j], a[i], bfr[j]);
        }

#pragma unroll
        for (int i = 0; i < 8; i++) {
            int row = r0 + ty*8 + i;
            float* op = g_voh[set] + ((size_t)row*HH + h)*DD + n0 + tx*8;
            float4 o0, o1;
            o0.x = acc2[i][0].x; o0.y = acc2[i][0].y; o0.z = acc2[i][1].x; o0.w = acc2[i][1].y;
            o1.x = acc2[i][2].x; o1.y = acc2[i][2].y; o1.z = acc2[i][3].x; o1.w = acc2[i][3].y;
            *(float4*)op       = o0;
            *(float4*)(op + 4) = o1;
        }
    } else {
        int id = bx - 768;
        int h = id & 7, b = (id >> 3) & 31, set = id >> 8;

        if (tid < MM) ssid[tid] = g_sidx[b*MM + tid];
        __syncthreads();

        for (int i = tid; i < EE*DPH; i += 256) {
            int q = i >> 5, d = i & 31;
            sm.s.qh[d][q] = g_qp[set][(b*EE + q)*DD + h*DPH + d];
        }
        for (int i = tid; i < MM*DPH; i += 256) {
            int m = i >> 5, d = i & 31;
            sm.s.kh[d][m] = g_kp[set][(size_t)ssid[m]*DD + h*DPH + d];
        }
        __syncthreads();

        int q0 = (tid >> 4) * 3;
        int m0 = (tid & 15) * 6;
        float acc[3][6];
#pragma unroll
        for (int i = 0; i < 3; i++)
#pragma unroll
            for (int j = 0; j < 6; j++) acc[i][j] = 0.f;

#pragma unroll 8
        for (int kk = 0; kk < DPH; kk++) {
            float qv[3], kv[6];
#pragma unroll
            for (int i = 0; i < 3; i++) qv[i] = sm.s.qh[kk][q0 + i];
#pragma unroll
            for (int j = 0; j < 6; j++) kv[j] = sm.s.kh[kk][m0 + j];
#pragma unroll
            for (int i = 0; i < 3; i++)
#pragma unroll
                for (int j = 0; j < 6; j++) acc[i][j] += qv[i] * kv[j];
        }

        const float scale = 0.17677669529663687f;
#pragma unroll
        for (int i = 0; i < 3; i++) {
            float* sp = &g_sc[set][((size_t)(b*EE + q0 + i)*HH + h)*MM + m0];
#pragma unroll
            for (int j = 0; j < 6; j++) sp[j] = acc[i][j] * scale;
        }
    }
}

// ---------------- combine v9: 2 q-groups x 4 d-quarters; 12q x 64d per warp ----------------
__shared__ int    s_ml[MAXML];
__shared__ float  s_al[SCAP][QH*HH];   // 6 KB
__shared__ float  s_mx[QH*HH];
__shared__ float  s_is[QH*HH];
__shared__ float2 s_par[QH][4];        // per-q (sum, sumsq) per d-quarter

// accumulate n mentions into acc[12] (float2 each); warp covers 64 d at dbase
__device__ __forceinline__ void accum12(
    float2 acc[12], const float* __restrict__ vohb,
    int base, int n, int qg, int dbase)
{
    for (int i = 0; i < n; i++) {
        const float* vrow = vohb + (size_t)s_ml[base + i]*(HH*DD) + dbase;
        float2 v[8];
#pragma unroll
        for (int h = 0; h < 8; h++) v[h] = ldg2(vrow + h*DD);
        const float* arow = s_al[i] + qg*12*8;
#pragma unroll
        for (int t = 0; t < 12; t++) {
            float4 a0 = *(const float4*)&arow[t*8];      // broadcast LDS.128
            float4 a1 = *(const float4*)&arow[t*8 + 4];
            fma2(acc[t], make_float2(a0.x, a0.x), v[0]);
            fma2(acc[t], make_float2(a0.y, a0.y), v[1]);
            fma2(acc[t], make_float2(a0.z, a0.z), v[2]);
            fma2(acc[t], make_float2(a0.w, a0.w), v[3]);
            fma2(acc[t], make_float2(a1.x, a1.x), v[4]);
            fma2(acc[t], make_float2(a1.y, a1.y), v[5]);
            fma2(acc[t], make_float2(a1.z, a1.z), v[6]);
            fma2(acc[t], make_float2(a1.w, a1.w), v[7]);
        }
    }
}

__global__ __launch_bounds__(256, 4) void k_combine(
    const float* __restrict__ ent,
    const float* __restrict__ b1, const float* __restrict__ ln1,
    const float* __restrict__ b2, const float* __restrict__ ln2,
    float* __restrict__ out)
{
    int e = blockIdx.x, b = blockIdx.y, z = blockIdx.z;
    int set = z >> 1, half = z & 1;
    int q0 = half * QH;
    int tid = threadIdx.x, lane = tid & 31, wid = tid >> 5;
    int qg = wid >> 2;            // 0..1: q-group (12 q each)
    int dq = wid & 3;             // 0..3: d-quarter
    int dbase = dq*64 + lane*2;   // 2 floats per thread

    int cnt = g_mcnt[b*EE + e];
    if (tid < MAXML) s_ml[tid] = (tid < cnt) ? g_mlist[(b*EE + e)*MAXML + tid] : 0;
    __syncthreads();

    const float* vohb = g_voh[set] + (size_t)b*MM*HH*DD;
    const float* bbp  = (set ? b2 : b1) + 3*DD;
    const float* ln   = (set ? ln2 : ln1);
    size_t outb = ((size_t)set*BB + b) * PAIRS * DD;

    float2 bo = ldg2(bbp + dbase);
    float2 x[12];

    if (cnt == 1) {
        const float* vrow = vohb + (size_t)s_ml[0]*(HH*DD) + dbase;
        float2 s = bo;
#pragma unroll
        for (int h = 0; h < HH; h++) {
            float2 v = ldg2(vrow + h*DD);
            s.x += v.x; s.y += v.y;
        }
#pragma unroll
        for (int t = 0; t < 12; t++) {
            int q = q0 + qg*12 + t;
            float2 ev = ldg2(ent + (size_t)(b*EE + q)*DD + dbase);
            x[t].x = s.x + ev.x; x[t].y = s.y + ev.y;
        }
    } else {
        const float* scb = g_sc[set] + ((size_t)b*EE + q0)*HH*MM;

        float2 acc[12];
#pragma unroll
        for (int t = 0; t < 12; t++) acc[t] = make_float2(0.f, 0.f);

        if (cnt <= SCAP) {
            for (int t = tid; t < QH*HH; t += 256) {
                const float* sp = scb + (size_t)t*MM;
                float sv[SCAP];
                float mx = -1e30f;
                for (int i = 0; i < cnt; i++) { sv[i] = sp[s_ml[i]]; mx = fmaxf(mx, sv[i]); }
                float s = 0.f;
                for (int i = 0; i < cnt; i++) { sv[i] = __expf(sv[i] - mx); s += sv[i]; }
                float inv = 1.f / s;
                for (int i = 0; i < cnt; i++) s_al[i][t] = sv[i] * inv;
            }
            __syncthreads();
            accum12(acc, vohb, 0, cnt, qg, dbase);
        } else {
            for (int t = tid; t < QH*HH; t += 256) {
                const float* sp = scb + (size_t)t*MM;
                float mx = -1e30f;
                for (int i = 0; i < cnt; i++) mx = fmaxf(mx, sp[s_ml[i]]);
                float s = 0.f;
                for (int i = 0; i < cnt; i++) s += __expf(sp[s_ml[i]] - mx);
                s_mx[t] = mx; s_is[t] = 1.f / s;
            }
            __syncthreads();
            for (int base = 0; base < cnt; base += SCAP) {
                int n = min(SCAP, cnt - base);
                for (int idx = tid; idx < QH*HH*n; idx += 256) {
                    int i = idx / (QH*HH), t = idx - i*(QH*HH);
                    float sv = scb[(size_t)t*MM + s_ml[base + i]];
                    s_al[i][t] = __expf(sv - s_mx[t]) * s_is[t];
                }
                __syncthreads();
                accum12(acc, vohb, base, n, qg, dbase);
                __syncthreads();
            }
        }

#pragma unroll
        for (int t = 0; t < 12; t++) {
            int q = q0 + qg*12 + t;
            float2 ev = ldg2(ent + (size_t)(b*EE + q)*DD + dbase);
            x[t].x = acc[t].x + bo.x + ev.x;
            x[t].y = acc[t].y + bo.y + ev.y;
        }
    }

    // per-q partial (sum, sumsq) over this warp's 64 columns
#pragma unroll
    for (int t = 0; t < 12; t++) {
        float sm = x[t].x + x[t].y;
        float s2 = x[t].x*x[t].x + x[t].y*x[t].y;
#pragma unroll
        for (int o = 16; o > 0; o >>= 1) {
            sm += __shfl_xor_sync(0xffffffffu, sm, o);
            s2 += __shfl_xor_sync(0xffffffffu, s2, o);
        }
        if (lane == 0) s_par[qg*12 + t][dq] = make_float2(sm, s2);
    }
    __syncthreads();

    float2 gm = ldg2(ln + dbase);
    float2 bt = ldg2(ln + DD + dbase);
#pragma unroll
    for (int t = 0; t < 12; t++) {
        int lq = qg*12 + t;
        float2 p0 = s_par[lq][0], p1 = s_par[lq][1];
        float2 p2 = s_par[lq][2], p3 = s_par[lq][3];
        float mu  = (p0.x + p1.x + p2.x + p3.x) * (1.f/DD);
        float var = fmaxf((p0.y + p1.y + p2.y + p3.y) * (1.f/DD) - mu*mu, 0.f);
        float rs  = rsqrtf(var + 1e-5f);
        int q = q0 + lq;
        int orow = set ? (q*EE + e) : (e*EE + q);
        float2 o;
        o.x = (x[t].x - mu)*rs*gm.x + bt.x;
        o.y = (x[t].y - mu)*rs*gm.y + bt.y;
        *(float2*)(out + outb + (size_t)orow*DD + dbase) = o;
    }
}

// ---------------- launch ----------------
extern "C" void kernel_launch(void* const* d_in, const int* in_sizes, int n_in,
                              void* d_out, int out_size) {
    const void*  info = d_in[0];
    const float* ent  = (const float*)d_in[2];
    const float* men  = (const float*)d_in[3];
    const float* sen  = (const float*)d_in[4];
    const float* W1   = (const float*)d_in[5];
    const float* b1   = (const float*)d_in[6];
    const float* ln1  = (const float*)d_in[7];
    const float* W2   = (const float*)d_in[8];
    const float* b2   = (const float*)d_in[9];
    const float* ln2  = (const float*)d_in[10];
    float* out = (float*)d_out;

    k_prep<<<BB, 128>>>(info);
    k_proj_all<<<192, 256>>>(ent, men, sen, W1, b1, W2, b2);
    k_vs<<<1280, 256>>>(W1, W2);
    k_combine<<<dim3(EE, BB, 4), 256>>>(ent, b1, ln1, b2, ln2, out);
}

// round 14
// speedup vs baseline: 1.1582x; 1.0433x over previous
#include <cuda_runtime.h>

#define BB   32
#define EE   48
#define MM   96
#define DD   256
#define HH   8
#define DPH  32
#define PAIRS (EE*EE)
#define MAXML 64
#define SCAP 8
#define QH   24

// ---------------- scratch ----------------
__device__ int   g_sidx[BB*MM];
__device__ int   g_mlist[BB*EE*MAXML];
__device__ int   g_mcnt [BB*EE];
__device__ float g_qp [2][BB*EE*DD];
__device__ float g_kp [2][BB*MM*DD];
__device__ float g_v  [2][BB*MM*DD];
__device__ float g_voh[2][BB*MM*HH*DD];
__device__ float g_sc [2][BB*EE*HH*MM];

__device__ __forceinline__ void fma2(float2& d, float2 a, float2 b) {
    unsigned long long dd = *(unsigned long long*)&d;
    unsigned long long aa = *(unsigned long long*)&a;
    unsigned long long bb = *(unsigned long long*)&b;
    asm("fma.rn.f32x2 %0, %1, %2, %0;" : "+l"(dd) : "l"(aa), "l"(bb));
    d = *(float2*)&dd;
}

__device__ __forceinline__ float4 ldg4(const float* p) {
    return __ldg((const float4*)p);
}

__device__ __forceinline__ void pf_l1(const float* p) {
    asm volatile("prefetch.global.L1 [%0];" :: "l"(p));
}

// ---------------- prep: one block per doc ----------------
__global__ void k_prep(const void* info) {
    int b = blockIdx.x, tid = threadIdx.x;
    __shared__ int smid[MM];
    __shared__ int s[128];
    const int* p32 = (const int*)info;
    int mx = 0;
    for (int r = tid; r < BB*MM; r += 128) mx = max(mx, p32[r*6 + 4]);
    s[tid] = mx; __syncthreads();
    for (int o = 64; o > 0; o >>= 1) { if (tid < o) s[tid] = max(s[tid], s[tid+o]); __syncthreads(); }
    int is32 = (s[0] > 0);
    for (int m = tid; m < MM; m += 128) {
        int r = b*MM + m;
        int e, sidx;
        if (is32) { e = p32[r*6 + 0]; sidx = p32[r*6 + 4]; }
        else {
            const long long* p64 = (const long long*)info;
            e = (int)p64[r*6 + 0]; sidx = (int)p64[r*6 + 4];
        }
        smid[m] = e; g_sidx[r] = sidx;
    }
    __syncthreads();
    for (int e = tid; e < EE; e += 128) {
        int target = b*EE + e;
        int cnt = 0;
        for (int m = 0; m < MM; m++) {
            if (smid[m] == target && cnt < MAXML)
                g_mlist[target*MAXML + cnt++] = m;
        }
        g_mcnt[target] = cnt;
    }
}

// ---------------- all 6 projections: 128x128 tiles, KSTEP=16, f32x2 ----------------
__global__ __launch_bounds__(256, 2) void k_proj_all(
    const float* __restrict__ ent, const float* __restrict__ men, const float* __restrict__ sen,
    const float* __restrict__ W1, const float* __restrict__ b1,
    const float* __restrict__ W2, const float* __restrict__ b2)
{
    __shared__ float2 As2[16][128];
    __shared__ float2 Ws2[16][64];

    int blk = blockIdx.x;
    int cb = blk & 1, rb = blk >> 1;
    int set = rb / 60; int r = rb % 60;
    const float* A; int gather = 0, type, row0;
    if (r < 12)      { type = 0; row0 = r*128;      A = ent; }
    else if (r < 36) { type = 1; row0 = (r-12)*128; A = sen; gather = 1; }
    else             { type = 2; row0 = (r-36)*128; A = men; }
    const float* W  = (set ? W2 : W1) + type*DD*DD;
    const float* bi = (set ? b2 : b1) + type*DD;
    float* C = (type == 0) ? g_qp[set] : (type == 1 ? g_kp[set] : g_v[set]);
    int n0 = cb*128;

    int tid = threadIdx.x;
    int tx = tid & 15, ty = tid >> 4;

    int am  = tid >> 1;
    int akq = (tid & 1) * 8;
    int arow = row0 + am;
    int asrc = gather ? g_sidx[arow] : arow;
    const float* aptr = A + (size_t)asrc*DD + akq;
    int wk = tid >> 4;
    int wn = (tid & 15) * 8;
    const float* wptr = W + (size_t)wk*DD + n0 + wn;
    int wp = (tid & 15) * 4;

    float2 acc2[8][4];
#pragma unroll
    for (int i = 0; i < 8; i++)
#pragma unroll
        for (int j = 0; j < 4; j++) acc2[i][j] = make_float2(0.f, 0.f);

    for (int k0 = 0; k0 < DD; k0 += 16) {
        float4 a0 = *(const float4*)(aptr + k0);
        float4 a1 = *(const float4*)(aptr + k0 + 4);
        float4 w0 = *(const float4*)(wptr + (size_t)k0*DD);
        float4 w1 = *(const float4*)(wptr + (size_t)k0*DD + 4);
        As2[akq+0][am] = make_float2(a0.x, a0.x);
        As2[akq+1][am] = make_float2(a0.y, a0.y);
        As2[akq+2][am] = make_float2(a0.z, a0.z);
        As2[akq+3][am] = make_float2(a0.w, a0.w);
        As2[akq+4][am] = make_float2(a1.x, a1.x);
        As2[akq+5][am] = make_float2(a1.y, a1.y);
        As2[akq+6][am] = make_float2(a1.z, a1.z);
        As2[akq+7][am] = make_float2(a1.w, a1.w);
        Ws2[wk][wp]   = make_float2(w0.x, w0.y);
        Ws2[wk][wp+1] = make_float2(w0.z, w0.w);
        Ws2[wk][wp+2] = make_float2(w1.x, w1.y);
        Ws2[wk][wp+3] = make_float2(w1.z, w1.w);
        __syncthreads();
#pragma unroll
        for (int kk = 0; kk < 16; kk++) {
            float2 a[8], bfr[4];
#pragma unroll
            for (int i = 0; i < 8; i++) a[i] = As2[kk][ty*8 + i];
#pragma unroll
            for (int j = 0; j < 4; j++) bfr[j] = Ws2[kk][tx*4 + j];
#pragma unroll
            for (int i = 0; i < 8; i++)
#pragma unroll
                for (int j = 0; j < 4; j++) fma2(acc2[i][j], a[i], bfr[j]);
        }
        __syncthreads();
    }

    float bj[8];
#pragma unroll
    for (int j = 0; j < 8; j++) bj[j] = bi[n0 + tx*8 + j];
#pragma unroll
    for (int i = 0; i < 8; i++) {
        int row = row0 + ty*8 + i;
        float* crow = C + (size_t)row*DD + n0 + tx*8;
        float4 o0, o1;
        o0.x = acc2[i][0].x+bj[0]; o0.y = acc2[i][0].y+bj[1];
        o0.z = acc2[i][1].x+bj[2]; o0.w = acc2[i][1].y+bj[3];
        o1.x = acc2[i][2].x+bj[4]; o1.y = acc2[i][2].y+bj[5];
        o1.z = acc2[i][3].x+bj[6]; o1.w = acc2[i][3].y+bj[7];
        *(float4*)crow       = o0;
        *(float4*)(crow + 4) = o1;
    }
}

// ---------------- fused voh (blocks 0..767) + scores (blocks 768..1279) ----------------
struct SmemVoh { float2 As2[32][128]; float2 Ws2[32][64]; };
struct SmemSc  { float qh[32][48]; float kh[32][96]; };

__global__ __launch_bounds__(256) void k_vs(const float* __restrict__ W1, const float* __restrict__ W2) {
    __shared__ union { SmemVoh v; SmemSc s; } sm;
    int bx = blockIdx.x;
    int tid = threadIdx.x;

    if (bx < 768) {
        int x = bx % 24, rest = bx / 24;
        int y = rest & 1, z = rest >> 1;
        int set = z >> 3, h = z & 7;
        const float* Wout = (set ? W2 : W1) + 3*DD*DD + h*DPH*DD;
        const float* V = g_v[set];
        int r0 = x * 128, n0 = y * 128;
        int tx = tid & 15, ty = tid >> 4;

        {
            int rr = tid >> 1, kq = (tid & 1) * 16;
            const float* ap = V + (size_t)(r0 + rr)*DD + h*DPH + kq;
#pragma unroll
            for (int c = 0; c < 4; c++) {
                float4 av = *(const float4*)(ap + c*4);
                sm.v.As2[kq + c*4 + 0][rr] = make_float2(av.x, av.x);
                sm.v.As2[kq + c*4 + 1][rr] = make_float2(av.y, av.y);
                sm.v.As2[kq + c*4 + 2][rr] = make_float2(av.z, av.z);
                sm.v.As2[kq + c*4 + 3][rr] = make_float2(av.w, av.w);
            }
        }
        {
            int wk = tid >> 5, wp = (tid & 31) * 2, wn = (tid & 31) * 4;
#pragma unroll
            for (int s = 0; s < 4; s++) {
                float4 wv = *(const float4*)(Wout + (size_t)(wk + 8*s)*DD + n0 + wn);
                sm.v.Ws2[wk + 8*s][wp]   = make_float2(wv.x, wv.y);
                sm.v.Ws2[wk + 8*s][wp+1] = make_float2(wv.z, wv.w);
            }
        }
        __syncthreads();

        float2 acc2[8][4];
#pragma unroll
        for (int i = 0; i < 8; i++)
#pragma unroll
            for (int j = 0; j < 4; j++) acc2[i][j] = make_float2(0.f, 0.f);

#pragma unroll
        for (int kk = 0; kk < 32; kk++) {
            float2 a[8], bfr[4];
#pragma unroll
            for (int i = 0; i < 8; i++) a[i] = sm.v.As2[kk][ty*8 + i];
#pragma unroll
            for (int j = 0; j < 4; j++) bfr[j] = sm.v.Ws2[kk][tx*4 + j];
#pragma unroll
            for (int i = 0; i < 8; i++)
#pragma unroll
                for (int j = 0; j < 4; j++) fma2(acc2[i][j], a[i], bfr[j]);
        }

#pragma unroll
        for (int i = 0; i < 8; i++) {
            int row = r0 + ty*8 + i;
            float* op = g_voh[set] + ((size_t)row*HH + h)*DD + n0 + tx*8;
            float4 o0, o1;
            o0.x = acc2[i][0].x; o0.y = acc2[i][0].y; o0.z = acc2[i][1].x; o0.w = acc2[i][1].y;
            o1.x = acc2[i][2].x; o1.y = acc2[i][2].y; o1.z = acc2[i][3].x; o1.w = acc2[i][3].y;
            *(float4*)op       = o0;
            *(float4*)(op + 4) = o1;
        }
    } else {
        int id = bx - 768;
        int h = id & 7, b = (id >> 3) & 31, set = id >> 8;

        for (int i = tid; i < EE*DPH; i += 256) {
            int q = i >> 5, d = i & 31;
            sm.s.qh[d][q] = g_qp[set][(b*EE + q)*DD + h*DPH + d];
        }
        for (int i = tid; i < MM*DPH; i += 256) {
            int m = i >> 5, d = i & 31;
            sm.s.kh[d][m] = g_kp[set][(b*MM + m)*DD + h*DPH + d];
        }
        __syncthreads();

        int q0 = (tid >> 4) * 3;
        int m0 = (tid & 15) * 6;
        float acc[3][6];
#pragma unroll
        for (int i = 0; i < 3; i++)
#pragma unroll
            for (int j = 0; j < 6; j++) acc[i][j] = 0.f;

#pragma unroll 8
        for (int kk = 0; kk < DPH; kk++) {
            float qv[3], kv[6];
#pragma unroll
            for (int i = 0; i < 3; i++) qv[i] = sm.s.qh[kk][q0 + i];
#pragma unroll
            for (int j = 0; j < 6; j++) kv[j] = sm.s.kh[kk][m0 + j];
#pragma unroll
            for (int i = 0; i < 3; i++)
#pragma unroll
                for (int j = 0; j < 6; j++) acc[i][j] += qv[i] * kv[j];
        }

        const float scale = 0.17677669529663687f;
#pragma unroll
        for (int i = 0; i < 3; i++) {
            float* sp = &g_sc[set][((size_t)(b*EE + q0 + i)*HH + h)*MM + m0];
#pragma unroll
            for (int j = 0; j < 6; j++) sp[j] = acc[i][j] * scale;
        }
    }
}

// fused single-pass LayerNorm + write (x[8] at d0..d0+3, d1..d1+3)
__device__ __forceinline__ void ln_write(
    float* x, const float* ln, float* op, int d0, int d1)
{
    float sm = 0.f, s2 = 0.f;
#pragma unroll
    for (int j = 0; j < 8; j++) { sm += x[j]; s2 += x[j]*x[j]; }
#pragma unroll
    for (int o = 16; o > 0; o >>= 1) {
        sm += __shfl_xor_sync(0xffffffffu, sm, o);
        s2 += __shfl_xor_sync(0xffffffffu, s2, o);
    }
    float mu  = sm * (1.f/DD);
    float var = fmaxf(s2 * (1.f/DD) - mu*mu, 0.f);
    float rs  = rsqrtf(var + 1e-5f);

    float4 gm0 = ldg4(ln + d0),      gm1 = ldg4(ln + d1);
    float4 bt0 = ldg4(ln + DD + d0), bt1 = ldg4(ln + DD + d1);
    float4 o0, o1;
    o0.x = (x[0]-mu)*rs*gm0.x + bt0.x; o0.y = (x[1]-mu)*rs*gm0.y + bt0.y;
    o0.z = (x[2]-mu)*rs*gm0.z + bt0.z; o0.w = (x[3]-mu)*rs*gm0.w + bt0.w;
    o1.x = (x[4]-mu)*rs*gm1.x + bt1.x; o1.y = (x[5]-mu)*rs*gm1.y + bt1.y;
    o1.z = (x[6]-mu)*rs*gm1.z + bt1.z; o1.w = (x[7]-mu)*rs*gm1.w + bt1.w;
    *(float4*)(op + d0) = o0;
    *(float4*)(op + d1) = o1;
}

// ---------------- combine v6 + L1 prefetch of voh/ent during softmax ----------------
__shared__ int   s_ml[MAXML];
__shared__ float s_al[SCAP][QH*HH];
__shared__ float s_mx[QH*HH];
__shared__ float s_is[QH*HH];

__device__ __forceinline__ void accum_chunk(
    float2 acc2[3][4], const float* __restrict__ vohb,
    int base, int n, int wid, int d0, int d1)
{
    for (int i = 0; i < n; i++) {
        const float* vrow = vohb + (size_t)s_ml[base + i]*(HH*DD);
        const float* arow = s_al[i];
#pragma unroll
        for (int hq = 0; hq < 2; hq++) {
            float4 a[3];
#pragma unroll
            for (int t = 0; t < 3; t++)
                a[t] = *(const float4*)&arow[(wid + 8*t)*8 + hq*4];
#pragma unroll
            for (int hh = 0; hh < 4; hh++) {
                const float* vp = vrow + (hq*4 + hh)*DD;
                float4 v0 = ldg4(vp + d0);
                float4 v1 = ldg4(vp + d1);
                float2 v0a = make_float2(v0.x, v0.y), v0b = make_float2(v0.z, v0.w);
                float2 v1a = make_float2(v1.x, v1.y), v1b = make_float2(v1.z, v1.w);
#pragma unroll
                for (int t = 0; t < 3; t++) {
                    float av = (hh == 0) ? a[t].x : (hh == 1) ? a[t].y : (hh == 2) ? a[t].z : a[t].w;
                    float2 aa = make_float2(av, av);
                    fma2(acc2[t][0], aa, v0a);
                    fma2(acc2[t][1], aa, v0b);
                    fma2(acc2[t][2], aa, v1a);
                    fma2(acc2[t][3], aa, v1b);
                }
            }
        }
    }
}

__global__ __launch_bounds__(256, 4) void k_combine(
    const float* __restrict__ ent,
    const float* __restrict__ b1, const float* __restrict__ ln1,
    const float* __restrict__ b2, const float* __restrict__ ln2,
    float* __restrict__ out)
{
    int e = blockIdx.x, b = blockIdx.y, z = blockIdx.z;
    int set = z >> 1, half = z & 1;
    int q0 = half * QH;
    int tid = threadIdx.x, lane = tid & 31, wid = tid >> 5;

    int cnt = g_mcnt[b*EE + e];
    if (tid < MAXML) s_ml[tid] = (tid < cnt) ? g_mlist[(b*EE + e)*MAXML + tid] : 0;
    __syncthreads();

    const float* vohb = g_voh[set] + (size_t)b*MM*HH*DD;
    const float* bbp  = (set ? b2 : b1) + 3*DD;
    const float* ln   = (set ? ln2 : ln1);
    int d0 = lane*4, d1 = 128 + lane*4;
    size_t outb = ((size_t)set*BB + b) * PAIRS * DD;

    // ---- prefetch: pull voh rows (one 128B line/thread; covers cnt<=4 fully)
    // and the ent rows needed by the epilogue, overlapping the softmax phase ----
    {
        int i = tid >> 6;
        if (i < cnt)
            pf_l1(vohb + (size_t)s_ml[i]*(HH*DD) + (tid & 63)*32);
        pf_l1(ent + ((size_t)b*EE + q0)*DD + tid*24);   // 24*4B*256 = 24KB of this half's ent rows
    }

    if (cnt == 1) {
        const float* vrow = vohb + (size_t)s_ml[0]*(HH*DD);
        float4 bo0 = ldg4(bbp + d0), bo1 = ldg4(bbp + d1);
        float s[8];
        s[0]=bo0.x; s[1]=bo0.y; s[2]=bo0.z; s[3]=bo0.w;
        s[4]=bo1.x; s[5]=bo1.y; s[6]=bo1.z; s[7]=bo1.w;
#pragma unroll
        for (int h = 0; h < HH; h++) {
            float4 v0 = ldg4(vrow + h*DD + d0);
            float4 v1 = ldg4(vrow + h*DD + d1);
            s[0]+=v0.x; s[1]+=v0.y; s[2]+=v0.z; s[3]+=v0.w;
            s[4]+=v1.x; s[5]+=v1.y; s[6]+=v1.z; s[7]+=v1.w;
        }
#pragma unroll
        for (int t = 0; t < 3; t++) {
            int q = q0 + wid + 8*t;
            const float* er = ent + (size_t)(b*EE + q)*DD;
            float4 e0 = ldg4(er + d0), e1 = ldg4(er + d1);
            float x[8];
            x[0]=s[0]+e0.x; x[1]=s[1]+e0.y; x[2]=s[2]+e0.z; x[3]=s[3]+e0.w;
            x[4]=s[4]+e1.x; x[5]=s[5]+e1.y; x[6]=s[6]+e1.z; x[7]=s[7]+e1.w;
            int orow = set ? (q*EE + e) : (e*EE + q);
            ln_write(x, ln, out + outb + (size_t)orow*DD, d0, d1);
        }
        return;
    }

    const float* scb = g_sc[set] + (size_t)b*EE*HH*MM;

    float2 acc2[3][4];
#pragma unroll
    for (int t = 0; t < 3; t++)
#pragma unroll
        for (int j = 0; j < 4; j++) acc2[t][j] = make_float2(0.f, 0.f);

    if (cnt <= SCAP) {
        if (tid < QH*HH) {
            int lq = tid >> 3, h = tid & 7;
            const float* sp = scb + ((size_t)(q0 + lq)*HH + h)*MM;
            float sv[SCAP];
            float mx = -1e30f;
            for (int i = 0; i < cnt; i++) { sv[i] = sp[s_ml[i]]; mx = fmaxf(mx, sv[i]); }
            float s = 0.f;
            for (int i = 0; i < cnt; i++) { sv[i] = __expf(sv[i] - mx); s += sv[i]; }
            float inv = 1.f / s;
            for (int i = 0; i < cnt; i++) s_al[i][tid] = sv[i] * inv;
        }
        __syncthreads();
        accum_chunk(acc2, vohb, 0, cnt, wid, d0, d1);
    } else {
        for (int t = tid; t < QH*HH; t += 256) {
            int lq = t >> 3, h = t & 7;
            const float* sp = scb + ((size_t)(q0 + lq)*HH + h)*MM;
            float mx = -1e30f;
            for (int i = 0; i < cnt; i++) mx = fmaxf(mx, sp[s_ml[i]]);
            float s = 0.f;
            for (int i = 0; i < cnt; i++) s += __expf(sp[s_ml[i]] - mx);
            s_mx[t] = mx; s_is[t] = 1.f / s;
        }
        __syncthreads();
        for (int base = 0; base < cnt; base += SCAP) {
            int n = min(SCAP, cnt - base);
            for (int idx = tid; idx < QH*HH*n; idx += 256) {
                int i = idx / (QH*HH), t = idx - i*(QH*HH);
                int lq = t >> 3, h = t & 7;
                float sv = scb[((size_t)(q0 + lq)*HH + h)*MM + s_ml[base + i]];
                s_al[i][t] = __expf(sv - s_mx[t]) * s_is[t];
            }
            __syncthreads();
            accum_chunk(acc2, vohb, base, n, wid, d0, d1);
            __syncthreads();
        }
    }

    float4 bo0 = ldg4(bbp + d0), bo1 = ldg4(bbp + d1);
#pragma unroll
    for (int t = 0; t < 3; t++) {
        int q = q0 + wid + 8*t;
        const float* er = ent + (size_t)(b*EE + q)*DD;
        float4 e0 = ldg4(er + d0), e1 = ldg4(er + d1);
        float x[8];
        x[0] = acc2[t][0].x + bo0.x + e0.x; x[1] = acc2[t][0].y + bo0.y + e0.y;
        x[2] = acc2[t][1].x + bo0.z + e0.z; x[3] = acc2[t][1].y + bo0.w + e0.w;
        x[4] = acc2[t][2].x + bo1.x + e1.x; x[5] = acc2[t][2].y + bo1.y + e1.y;
        x[6] = acc2[t][3].x + bo1.z + e1.z; x[7] = acc2[t][3].y + bo1.w + e1.w;
        int orow = set ? (q*EE + e) : (e*EE + q);
        ln_write(x, ln, out + outb + (size_t)orow*DD, d0, d1);
    }
}

// ---------------- launch ----------------
extern "C" void kernel_launch(void* const* d_in, const int* in_sizes, int n_in,
                              void* d_out, int out_size) {
    const void*  info = d_in[0];
    const float* ent  = (const float*)d_in[2];
    const float* men  = (const float*)d_in[3];
    const float* sen  = (const float*)d_in[4];
    const float* W1   = (const float*)d_in[5];
    const float* b1   = (const float*)d_in[6];
    const float* ln1  = (const float*)d_in[7];
    const float* W2   = (const float*)d_in[8];
    const float* b2   = (const float*)d_in[9];
    const float* ln2  = (const float*)d_in[10];
    float* out = (float*)d_out;

    k_prep<<<BB, 128>>>(info);
    k_proj_all<<<240, 256>>>(ent, men, sen, W1, b1, W2, b2);
    k_vs<<<1280, 256>>>(W1, W2);
    k_combine<<<dim3(EE, BB, 4), 256>>>(ent, b1, ln1, b2, ln2, out);
}